// round 1
// baseline (speedup 1.0000x reference)
#include <cuda_runtime.h>
#include <math.h>

#define NMAX 100000
#define C 64
#define K 343

// scratch for normalized depthwise output (no cudaMalloc allowed)
__device__ float g_h[(size_t)NMAX * C];

// ---------------------------------------------------------------------------
// Kernel 1: depthwise submanifold conv + bias + GroupNorm(1 group)
// one warp per voxel, 2 channels per lane (float2)
// ---------------------------------------------------------------------------
__global__ void dwconv_gn_kernel(const float* __restrict__ x_feat,
                                 const int*   __restrict__ nbr,
                                 const float* __restrict__ W1,
                                 const float* __restrict__ b1,
                                 const float* __restrict__ gamma,
                                 const float* __restrict__ beta,
                                 int N) {
    int gwarp = (blockIdx.x * blockDim.x + threadIdx.x) >> 5;
    int lane  = threadIdx.x & 31;
    if (gwarp >= N) return;
    const int i = gwarp;

    const float2* featv = (const float2*)x_feat;
    const float2* W1v   = (const float2*)W1;
    const int* row = nbr + (long long)i * K;

    float2 acc = make_float2(0.f, 0.f);

    #pragma unroll 1
    for (int kb = 0; kb < K; kb += 32) {
        int k = kb + lane;
        int idx = (k < K) ? row[k] : N;          // sentinel N = invalid
        unsigned m = __ballot_sync(0xffffffffu, idx < N);
        while (m) {
            int j = __ffs(m) - 1;
            m &= m - 1;
            int src = __shfl_sync(0xffffffffu, idx, j);
            float2 f = featv[src * (C / 2) + lane];         // 256B coalesced gather
            float2 w = W1v[(kb + j) * (C / 2) + lane];      // L1-hot weights
            acc.x = fmaf(f.x, w.x, acc.x);
            acc.y = fmaf(f.y, w.y, acc.y);
        }
    }

    float2 bb = ((const float2*)b1)[lane];
    acc.x += bb.x; acc.y += bb.y;

    // GroupNorm over 64 channels (population variance)
    float s  = acc.x + acc.y;
    float s2 = acc.x * acc.x + acc.y * acc.y;
    #pragma unroll
    for (int o = 16; o > 0; o >>= 1) {
        s  += __shfl_xor_sync(0xffffffffu, s,  o);
        s2 += __shfl_xor_sync(0xffffffffu, s2, o);
    }
    float mu  = s  * (1.f / 64.f);
    float var = s2 * (1.f / 64.f) - mu * mu;
    float inv = rsqrtf(var + 1e-5f);

    float2 g  = ((const float2*)gamma)[lane];
    float2 be = ((const float2*)beta)[lane];
    float2 o;
    o.x = (acc.x - mu) * inv * g.x + be.x;
    o.y = (acc.y - mu) * inv * g.y + be.y;
    ((float2*)g_h)[(size_t)i * (C / 2) + lane] = o;
}

// ---------------------------------------------------------------------------
// Kernel 2: h @ W2 + b2 -> exact GELU -> @ W3 + b3 -> + x_feat
// 32-voxel tile per 256-thread block, register-blocked fp32 GEMMs
// ---------------------------------------------------------------------------
__global__ __launch_bounds__(256)
void mlp_kernel(const float* __restrict__ x_feat,
                const float* __restrict__ W2, const float* __restrict__ b2,
                const float* __restrict__ W3, const float* __restrict__ b3,
                float* __restrict__ out, int N) {
    __shared__ float sh[32 * 256];   // 32KB; first 2048 floats reused as h tile
    const int t  = threadIdx.x;
    const int v0 = blockIdx.x * 32;

    // ---- load h tile: 32 voxels x 64 ch = 2048 floats (512 float4) ----
    {
        float4* sh4 = (float4*)sh;
        const float4* hv = (const float4*)(g_h + (size_t)v0 * C);
        #pragma unroll
        for (int it = 0; it < 2; ++it) {
            int idx = t + it * 256;                    // float4 index
            float4 val = make_float4(0.f, 0.f, 0.f, 0.f);
            if (v0 + (idx >> 4) < N) val = hv[idx];
            sh4[idx] = val;
        }
    }
    __syncthreads();

    // ---- GEMM1: hid[vi] = b2[j] + sum_k h[vi][k] * W2[k][j],  j = t ----
    const int j = t;
    float hid[32];
    {
        float b2j = b2[j];
        #pragma unroll
        for (int vi = 0; vi < 32; ++vi) hid[vi] = b2j;

        const float4* sh4 = (const float4*)sh;
        #pragma unroll
        for (int k4 = 0; k4 < 16; ++k4) {
            float w0 = W2[(4 * k4 + 0) * 256 + j];
            float w1 = W2[(4 * k4 + 1) * 256 + j];
            float w2 = W2[(4 * k4 + 2) * 256 + j];
            float w3 = W2[(4 * k4 + 3) * 256 + j];
            #pragma unroll
            for (int vi = 0; vi < 32; ++vi) {
                float4 hv = sh4[vi * 16 + k4];          // warp broadcast
                hid[vi] = fmaf(hv.x, w0, hid[vi]);
                hid[vi] = fmaf(hv.y, w1, hid[vi]);
                hid[vi] = fmaf(hv.z, w2, hid[vi]);
                hid[vi] = fmaf(hv.w, w3, hid[vi]);
            }
        }
    }
    __syncthreads();   // all reads of h tile done

    // ---- exact GELU, stage hidden to smem [32][256] ----
    #pragma unroll
    for (int vi = 0; vi < 32; ++vi) {
        float x = hid[vi];
        sh[vi * 256 + j] = 0.5f * x * (1.f + erff(x * 0.7071067811865475f));
    }
    __syncthreads();

    // ---- GEMM2: out[vi][c] = b3[c] + sum_j g[vi][j] * W3[j][c] + residual ----
    const int c     = t & 63;
    const int vbase = (t >> 6) * 8;   // 4 groups x 8 voxels
    float acc[8];
    {
        float b3c = b3[c];
        #pragma unroll
        for (int vi = 0; vi < 8; ++vi) acc[vi] = b3c;

        const float4* sh4 = (const float4*)sh;
        #pragma unroll
        for (int j4 = 0; j4 < 64; ++j4) {
            float w0 = W3[(4 * j4 + 0) * 64 + c];
            float w1 = W3[(4 * j4 + 1) * 64 + c];
            float w2 = W3[(4 * j4 + 2) * 64 + c];
            float w3 = W3[(4 * j4 + 3) * 64 + c];
            #pragma unroll
            for (int vi = 0; vi < 8; ++vi) {
                float4 g = sh4[(vbase + vi) * 64 + j4]; // warp broadcast
                acc[vi] = fmaf(g.x, w0, acc[vi]);
                acc[vi] = fmaf(g.y, w1, acc[vi]);
                acc[vi] = fmaf(g.z, w2, acc[vi]);
                acc[vi] = fmaf(g.w, w3, acc[vi]);
            }
        }
    }

    #pragma unroll
    for (int vi = 0; vi < 8; ++vi) {
        int v = v0 + vbase + vi;
        if (v < N)
            out[(size_t)v * C + c] = acc[vi] + x_feat[(size_t)v * C + c];
    }
}

// ---------------------------------------------------------------------------
extern "C" void kernel_launch(void* const* d_in, const int* in_sizes, int n_in,
                              void* d_out, int out_size) {
    const float* x_feat = (const float*)d_in[0];
    const int*   nbr    = (const int*)  d_in[1];
    const float* W1     = (const float*)d_in[2];
    const float* b1     = (const float*)d_in[3];
    const float* gamma  = (const float*)d_in[4];
    const float* beta   = (const float*)d_in[5];
    const float* W2     = (const float*)d_in[6];
    const float* b2     = (const float*)d_in[7];
    const float* W3     = (const float*)d_in[8];
    const float* b3     = (const float*)d_in[9];
    float* out = (float*)d_out;

    int N = in_sizes[0] / C;

    int blocks1 = (N + 7) / 8;          // 8 warps -> 8 voxels per 256-thread block
    dwconv_gn_kernel<<<blocks1, 256>>>(x_feat, nbr, W1, b1, gamma, beta, N);

    int blocks2 = (N + 31) / 32;        // 32 voxels per block
    mlp_kernel<<<blocks2, 256>>>(x_feat, W2, b2, W3, b3, out, N);
}

// round 3
// speedup vs baseline: 1.3510x; 1.3510x over previous
#include <cuda_runtime.h>
#include <math.h>
#include <stdint.h>

#define NMAX   100000
#define C      64
#define KTAPS  343
#define TILE_M 128

// scratch: depthwise+GN output, tf32-prerounded, row-major [N][64]
__device__ float4 g_h[(size_t)NMAX * 16];

__device__ __forceinline__ float to_tf32(float x) {
    asm("cvt.rna.tf32.f32 %0, %1;" : "=f"(x) : "f"(x));
    return x;
}
__device__ __forceinline__ uint32_t tf32_bits(float x) {
    uint32_t u;
    asm("cvt.rna.tf32.f32 %0, %1;" : "=r"(u) : "f"(x));
    return u;
}

// D += A * B   (m16n8k8, tf32, A row-major frag, B col-major frag)
#define MMA_TF32(d, a, b0, b1)                                                          \
    asm volatile("mma.sync.aligned.m16n8k8.row.col.f32.tf32.tf32.f32 "                  \
                 "{%0,%1,%2,%3}, {%4,%5,%6,%7}, {%8,%9}, {%0,%1,%2,%3};"                \
                 : "+f"((d)[0]), "+f"((d)[1]), "+f"((d)[2]), "+f"((d)[3])               \
                 : "r"((a)[0]), "r"((a)[1]), "r"((a)[2]), "r"((a)[3]),                  \
                   "r"(b0), "r"(b1))

// ---------------------------------------------------------------------------
// Kernel 1: depthwise submanifold conv + bias + GroupNorm (1 group)
// one warp per voxel, 2 channels/lane; writes tf32-rounded h to g_h
// ---------------------------------------------------------------------------
__global__ void dwconv_gn_kernel(const float* __restrict__ x_feat,
                                 const int*   __restrict__ nbr,
                                 const float* __restrict__ W1,
                                 const float* __restrict__ b1,
                                 const float* __restrict__ gamma,
                                 const float* __restrict__ beta,
                                 int N) {
    int gwarp = (blockIdx.x * blockDim.x + threadIdx.x) >> 5;
    int lane  = threadIdx.x & 31;
    if (gwarp >= N) return;
    const int i = gwarp;

    const float2* featv = (const float2*)x_feat;
    const float2* W1v   = (const float2*)W1;
    const int* row = nbr + (long long)i * KTAPS;

    float2 acc = make_float2(0.f, 0.f);

    #pragma unroll 1
    for (int kb = 0; kb < KTAPS; kb += 32) {
        int k = kb + lane;
        int idx = (k < KTAPS) ? row[k] : N;
        unsigned m = __ballot_sync(0xffffffffu, idx < N);
        while (m) {
            int j = __ffs(m) - 1;
            m &= m - 1;
            int src = __shfl_sync(0xffffffffu, idx, j);
            float2 f = featv[src * 32 + lane];
            float2 w = W1v[(kb + j) * 32 + lane];
            acc.x = fmaf(f.x, w.x, acc.x);
            acc.y = fmaf(f.y, w.y, acc.y);
        }
    }

    float2 bb = ((const float2*)b1)[lane];
    acc.x += bb.x; acc.y += bb.y;

    float s  = acc.x + acc.y;
    float s2 = acc.x * acc.x + acc.y * acc.y;
    #pragma unroll
    for (int o = 16; o > 0; o >>= 1) {
        s  += __shfl_xor_sync(0xffffffffu, s,  o);
        s2 += __shfl_xor_sync(0xffffffffu, s2, o);
    }
    float mu  = s  * (1.f / 64.f);
    float var = s2 * (1.f / 64.f) - mu * mu;
    float inv = rsqrtf(var + 1e-5f);

    float2 g  = ((const float2*)gamma)[lane];
    float2 be = ((const float2*)beta)[lane];
    float ox = (acc.x - mu) * inv * g.x + be.x;
    float oy = (acc.y - mu) * inv * g.y + be.y;

    ((float2*)g_h)[(size_t)i * 32 + lane] = make_float2(to_tf32(ox), to_tf32(oy));
}

// ---------------------------------------------------------------------------
// Kernel 2: tensor-core MLP via mma.sync tf32.
// 128 voxels / CTA, 8 warps; warp w owns rows 16w..16w+15.
// ---------------------------------------------------------------------------
#define XSTR  68                 // sX row stride (floats): banks 4*g+q all distinct
#define W2STR 264                // sW2 row stride: banks 8*q+g all distinct
#define W3STR 72                 // sW3 row stride: banks 8*q+g all distinct
#define OF_X   0
#define OF_W2  (128 * XSTR)                  // 8704
#define OF_W3  (OF_W2 + 64 * W2STR)          // 25600
#define OF_B2  (OF_W3 + 256 * W3STR)         // 44032
#define OF_B3  (OF_B2 + 256)                 // 44288
#define SMEM_FLOATS (OF_B3 + 64)             // 44352 floats = 177408 bytes

__global__ __launch_bounds__(256)
void mlp_mma_kernel(const float* __restrict__ x_feat,
                    const float* __restrict__ W2g, const float* __restrict__ b2,
                    const float* __restrict__ W3g, const float* __restrict__ b3,
                    float* __restrict__ out, int N) {
    extern __shared__ float sm[];
    float* sX  = sm + OF_X;
    float* sW2 = sm + OF_W2;
    float* sW3 = sm + OF_W3;
    float* sB2 = sm + OF_B2;
    float* sB3 = sm + OF_B3;

    const int t = threadIdx.x;
    const int v0 = blockIdx.x * TILE_M;

    // ---- stage X tile (zero-pad beyond N) ----
    #pragma unroll
    for (int i = 0; i < 8; ++i) {
        int idx = t + i * 256;                 // 0..2047 float4s
        int row = idx >> 4, qc = idx & 15;
        float4 v = make_float4(0.f, 0.f, 0.f, 0.f);
        if (v0 + row < N) v = g_h[(size_t)(v0 + row) * 16 + qc];
        *(float4*)(sX + row * XSTR + qc * 4) = v;
    }
    // ---- stage W2 [64][256] (tf32-rounded) ----
    #pragma unroll
    for (int i = 0; i < 16; ++i) {
        int idx = t + i * 256;                 // 0..4095 float4s
        int row = idx >> 6, qc = idx & 63;
        float4 v = ((const float4*)W2g)[row * 64 + qc];
        v.x = to_tf32(v.x); v.y = to_tf32(v.y); v.z = to_tf32(v.z); v.w = to_tf32(v.w);
        *(float4*)(sW2 + row * W2STR + qc * 4) = v;
    }
    // ---- stage W3 [256][64] (tf32-rounded) ----
    #pragma unroll
    for (int i = 0; i < 16; ++i) {
        int idx = t + i * 256;
        int row = idx >> 4, qc = idx & 15;
        float4 v = ((const float4*)W3g)[row * 16 + qc];
        v.x = to_tf32(v.x); v.y = to_tf32(v.y); v.z = to_tf32(v.z); v.w = to_tf32(v.w);
        *(float4*)(sW3 + row * W3STR + qc * 4) = v;
    }
    sB2[t] = b2[t];
    if (t < 64) sB3[t] = b3[t];
    __syncthreads();

    const int wid  = t >> 5, lane = t & 31;
    const int g    = lane >> 2, q = lane & 3;
    const int R0   = wid * 16;
    const int qh   = q >> 1, qs = q & 1;
    const int src1 = (lane & ~3) + qh;
    const int src2 = src1 + 2;

    // ---- A fragments of GEMM1 (K = 64, 8 k-steps), loaded once ----
    uint32_t A1[8][4];
    {
        const float* xb = sX + (R0 + g) * XSTR;
        #pragma unroll
        for (int ks = 0; ks < 8; ++ks) {
            A1[ks][0] = __float_as_uint(xb[ks * 8 + q]);
            A1[ks][1] = __float_as_uint(xb[8 * XSTR + ks * 8 + q]);
            A1[ks][2] = __float_as_uint(xb[ks * 8 + q + 4]);
            A1[ks][3] = __float_as_uint(xb[8 * XSTR + ks * 8 + q + 4]);
        }
    }

    float acc2[8][4];
    #pragma unroll
    for (int n = 0; n < 8; ++n)
        { acc2[n][0] = acc2[n][1] = acc2[n][2] = acc2[n][3] = 0.f; }

    #pragma unroll 1
    for (int ch = 0; ch < 4; ++ch) {
        const int cb = ch * 64;

        // ---- GEMM1 chunk: acc1[16 x 64] ----
        float acc1[8][4];
        #pragma unroll
        for (int n = 0; n < 8; ++n)
            { acc1[n][0] = acc1[n][1] = acc1[n][2] = acc1[n][3] = 0.f; }

        #pragma unroll
        for (int ks = 0; ks < 8; ++ks) {
            const float* wb  = sW2 + (ks * 8 + q) * W2STR + cb + g;
            const float* wb4 = wb + 4 * W2STR;
            #pragma unroll
            for (int nt = 0; nt < 8; ++nt) {
                uint32_t b0 = __float_as_uint(wb[nt * 8]);
                uint32_t b1 = __float_as_uint(wb4[nt * 8]);
                MMA_TF32(acc1[nt], A1[ks], b0, b1);
            }
        }

        // ---- bias + exact GELU + tf32 round + shuffle-permute C->A ----
        uint32_t A2[8][4];
        #pragma unroll
        for (int nt = 0; nt < 8; ++nt) {
            float2 bv = *(const float2*)(sB2 + cb + nt * 8 + 2 * q);
            float x0 = acc1[nt][0] + bv.x;
            float x1 = acc1[nt][1] + bv.y;
            float x2 = acc1[nt][2] + bv.x;
            float x3 = acc1[nt][3] + bv.y;
            uint32_t g0 = tf32_bits(0.5f * x0 * (1.f + erff(x0 * 0.70710678118654752f)));
            uint32_t g1 = tf32_bits(0.5f * x1 * (1.f + erff(x1 * 0.70710678118654752f)));
            uint32_t g2 = tf32_bits(0.5f * x2 * (1.f + erff(x2 * 0.70710678118654752f)));
            uint32_t g3 = tf32_bits(0.5f * x3 * (1.f + erff(x3 * 0.70710678118654752f)));
            uint32_t t0 = __shfl_sync(0xffffffffu, g0, src1);
            uint32_t t1 = __shfl_sync(0xffffffffu, g1, src1);
            uint32_t t2 = __shfl_sync(0xffffffffu, g2, src1);
            uint32_t t3 = __shfl_sync(0xffffffffu, g3, src1);
            uint32_t u0 = __shfl_sync(0xffffffffu, g0, src2);
            uint32_t u1 = __shfl_sync(0xffffffffu, g1, src2);
            uint32_t u2 = __shfl_sync(0xffffffffu, g2, src2);
            uint32_t u3 = __shfl_sync(0xffffffffu, g3, src2);
            A2[nt][0] = qs ? t1 : t0;
            A2[nt][1] = qs ? t3 : t2;
            A2[nt][2] = qs ? u1 : u0;
            A2[nt][3] = qs ? u3 : u2;
        }

        // ---- GEMM2 partial: acc2 += G_chunk @ W3[cb:cb+64, :] ----
        #pragma unroll
        for (int kk = 0; kk < 8; ++kk) {
            const float* wb  = sW3 + (cb + kk * 8 + q) * W3STR + g;
            const float* wb4 = wb + 4 * W3STR;
            #pragma unroll
            for (int nt2 = 0; nt2 < 8; ++nt2) {
                uint32_t b0 = __float_as_uint(wb[nt2 * 8]);
                uint32_t b1 = __float_as_uint(wb4[nt2 * 8]);
                MMA_TF32(acc2[nt2], A2[kk], b0, b1);
            }
        }
    }

    // ---- epilogue: + b3 + residual, store ----
    {
        const int v_lo = v0 + R0 + g;
        const int v_hi = v_lo + 8;
        #pragma unroll
        for (int nt2 = 0; nt2 < 8; ++nt2) {
            int col = nt2 * 8 + 2 * q;
            float2 bv = *(const float2*)(sB3 + col);
            if (v_lo < N) {
                float2 xr = *(const float2*)(x_feat + (size_t)v_lo * 64 + col);
                float2 o;
                o.x = acc2[nt2][0] + bv.x + xr.x;
                o.y = acc2[nt2][1] + bv.y + xr.y;
                *(float2*)(out + (size_t)v_lo * 64 + col) = o;
            }
            if (v_hi < N) {
                float2 xr = *(const float2*)(x_feat + (size_t)v_hi * 64 + col);
                float2 o;
                o.x = acc2[nt2][2] + bv.x + xr.x;
                o.y = acc2[nt2][3] + bv.y + xr.y;
                *(float2*)(out + (size_t)v_hi * 64 + col) = o;
            }
        }
    }
}

// ---------------------------------------------------------------------------
extern "C" void kernel_launch(void* const* d_in, const int* in_sizes, int n_in,
                              void* d_out, int out_size) {
    const float* x_feat = (const float*)d_in[0];
    const int*   nbr    = (const int*)  d_in[1];
    const float* W1     = (const float*)d_in[2];
    const float* b1     = (const float*)d_in[3];
    const float* gamma  = (const float*)d_in[4];
    const float* beta   = (const float*)d_in[5];
    const float* W2     = (const float*)d_in[6];
    const float* b2     = (const float*)d_in[7];
    const float* W3     = (const float*)d_in[8];
    const float* b3     = (const float*)d_in[9];
    float* out = (float*)d_out;

    int N = in_sizes[0] / C;
    int tiles = (N + TILE_M - 1) / TILE_M;

    static int smem_set = 0;
    if (!smem_set) {
        cudaFuncSetAttribute(mlp_mma_kernel, cudaFuncAttributeMaxDynamicSharedMemorySize,
                             SMEM_FLOATS * (int)sizeof(float));
        smem_set = 1;
    }

    int blocks1 = (N + 7) / 8;
    dwconv_gn_kernel<<<blocks1, 256>>>(x_feat, nbr, W1, b1, gamma, beta, N);

    mlp_mma_kernel<<<tiles, 256, SMEM_FLOATS * sizeof(float)>>>(
        x_feat, W2, b2, W3, b3, out, N);
}